// round 10
// baseline (speedup 1.0000x reference)
#include <cuda_runtime.h>
#include <cstdint>

// ---------------- problem constants ----------------
#define NTEXT 90000
#define NTOT  100000
#define NE    500000
#define NRELS 500
#define NS    5           // Bayesian samples
#define KP    272         // 266 padded to 272
#define COLS  2560        // 2 sides * 5 samples * 256 hidden
#define W1N   267264      // 256*1044

// ---------------- scratch (__device__ globals; no allocs allowed) ----------------
__device__ unsigned g_sk[NS][4][2];
__device__ float g_w1s[NS][W1N];          // sampled w1, row-major [256][1044]
__device__ float g_b1s[NS][256];
__device__ float g_w2s[NS * 256];
__device__ float g_qv[NS][256];
__device__ float g_b2mean;
__device__ float g_Wfull[KP * COLS];      // GEMM B
__device__ float g_Cp[NRELS * 1280];      // per-relation: rel@w1_r.T + qv + b1
__device__ float g_X[(size_t)NTOT * KP];  // GEMM A  (~109MB)
__device__ float g_AB[(size_t)NTOT * COLS]; // GEMM C (~1.02GB)
__device__ float g_deg_t[NTOT], g_deg_h[NTOT];
__device__ float g_s1f[2 * NTOT], g_s1r[2 * NTOT], g_s2f[2 * NTOT], g_s2r[2 * NTOT];
__device__ float g_f1[2 * NTOT], g_r1[2 * NTOT];

// ---------------- threefry2x32 (JAX-exact) ----------------
__device__ __forceinline__ unsigned rotl32(unsigned v, int r) { return (v << r) | (v >> (32 - r)); }

__device__ __forceinline__ void tf2(unsigned k0, unsigned k1, unsigned c0, unsigned c1,
                                    unsigned& o0, unsigned& o1) {
    unsigned ks2 = k0 ^ k1 ^ 0x1BD11BDAu;
    unsigned x0 = c0 + k0, x1 = c1 + k1;
#define TFR(r) x0 += x1; x1 = rotl32(x1, r); x1 ^= x0;
    TFR(13) TFR(15) TFR(26) TFR(6)  x0 += k1;  x1 += ks2 + 1u;
    TFR(17) TFR(29) TFR(16) TFR(24) x0 += ks2; x1 += k0 + 2u;
    TFR(13) TFR(15) TFR(26) TFR(6)  x0 += k0;  x1 += k1 + 3u;
    TFR(17) TFR(29) TFR(16) TFR(24) x0 += k1;  x1 += ks2 + 4u;
    TFR(13) TFR(15) TFR(26) TFR(6)  x0 += ks2; x1 += k0 + 5u;
#undef TFR
    o0 = x0; o1 = x1;
}

// partitionable random_bits(32): bits[i] = o0 ^ o1 of tf2(key, hi32(i)=0, lo32(i)=i)
__device__ __forceinline__ unsigned pbits(unsigned k0, unsigned k1, unsigned i) {
    unsigned o0, o1;
    tf2(k0, k1, 0u, i, o0, o1);
    return o0 ^ o1;
}

// bits -> N(0,1), matching jax _normal_real: u in [nextafter(-1,0), 1), sqrt(2)*erfinv(u)
__device__ __forceinline__ float bits2n(unsigned bits) {
    float f = __uint_as_float((bits >> 9) | 0x3f800000u) - 1.0f;
    // maxval-minval = 1.0f - (-0.99999994f) rounds to 2.0f in fp32 (what XLA computes)
    float u = __fadd_rn(__fmul_rn(f, 2.0f), -0.99999994f);
    u = fmaxf(u, -0.99999994f);
    return 1.41421356f * erfinvf(u);
}

__device__ __forceinline__ float softplusf(float x) {
    return fmaxf(x, 0.0f) + log1pf(expf(-fabsf(x)));
}

// ---------------- key derivation: key(42) -> fold_in(i) -> split(4) ----------------
// partitionable split: subkey j = both output words of tf2(key, (0, j))
__global__ void k_setup_keys() {
    if (threadIdx.x == 0 && blockIdx.x == 0) {
        for (int i = 0; i < NS; i++) {
            unsigned k0, k1;
            tf2(0u, 42u, 0u, (unsigned)i, k0, k1);            // fold_in (same in both modes)
            for (int j = 0; j < 4; j++)
                tf2(k0, k1, 0u, (unsigned)j, g_sk[i][j][0], g_sk[i][j][1]);
        }
    }
}

// ---------------- sample w1 (5 x 256 x 1044) ----------------
__global__ void k_gen_w1(const float* __restrict__ mu, const float* __restrict__ rho) {
    int tid = blockIdx.x * blockDim.x + threadIdx.x;
    if (tid >= NS * W1N) return;
    int s = tid / W1N, i = tid % W1N;
    unsigned b = pbits(g_sk[s][0][0], g_sk[s][0][1], (unsigned)i);
    g_w1s[s][i] = mu[i] + bits2n(b) * softplusf(rho[i]);
}

// ---------------- sample b1, w2, b2 ----------------
__global__ void k_gen_small(const float* __restrict__ b1mu, const float* __restrict__ b1rho,
                            const float* __restrict__ w2mu, const float* __restrict__ w2rho,
                            const float* __restrict__ b2mu, const float* __restrict__ b2rho) {
    int t = threadIdx.x;  // 0..255
    for (int s = 0; s < NS; s++) {
        unsigned bb = pbits(g_sk[s][1][0], g_sk[s][1][1], (unsigned)t);
        g_b1s[s][t] = b1mu[t] + bits2n(bb) * softplusf(b1rho[t]);
        unsigned bw = pbits(g_sk[s][2][0], g_sk[s][2][1], (unsigned)t);
        g_w2s[s * 256 + t] = w2mu[t] + bits2n(bw) * softplusf(w2rho[t]);
    }
    if (t == 0) {
        float acc = 0.f;
        for (int s = 0; s < NS; s++) {
            unsigned b2b = pbits(g_sk[s][3][0], g_sk[s][3][1], 0u);
            acc += b2mu[0] + bits2n(b2b) * softplusf(b2rho[0]);
        }
        g_b2mean = acc / 5.0f;
    }
}

// ---------------- qv_s = q @ w1_s[:, 0:256].T ----------------
__global__ void k_qv(const float* __restrict__ q) {
    int s = blockIdx.x, j = threadIdx.x;
    const float* w = &g_w1s[s][j * 1044];
    float acc = 0.f;
    for (int k = 0; k < 256; k++) acc += q[k] * w[k];
    g_qv[s][j] = acc;
}

// ---------------- repack GEMM-B: Wfull[k][side*1280 + s*256 + j] ----------------
__global__ void k_repack() {
    int idx = blockIdx.x * blockDim.x + threadIdx.x;
    if (idx >= KP * COLS) return;
    int k = idx / COLS, c = idx % COLS;
    float v = 0.f;
    if (k < 266) {
        int side = c / 1280, rem = c % 1280, s = rem / 256, j = rem % 256;
        int col = (k < 256) ? ((side ? 778 : 256) + k) : ((side ? 1034 : 512) + (k - 256));
        v = g_w1s[s][j * 1044 + col];
    }
    g_Wfull[idx] = v;
}

// ---------------- C'[r][s*256+j] = b1 + qv + rel[r] @ w1_r.T ----------------
__global__ void k_crel(const float* __restrict__ rel) {
    int r = blockIdx.x, s = blockIdx.y, j = threadIdx.x;
    __shared__ float rsm[256];
    rsm[j] = rel[r * 256 + j];
    __syncthreads();
    const float* w = &g_w1s[s][j * 1044 + 522];
    float acc = g_b1s[s][j] + g_qv[s][j];
    for (int k = 0; k < 256; k++) acc += rsm[k] * w[k];
    g_Cp[r * 1280 + s * 256 + j] = acc;
}

// ---------------- DDE (segment means) ----------------
__global__ void k_zero() {
    int i = blockIdx.x * blockDim.x + threadIdx.x;
    if (i < NTOT) { g_deg_t[i] = 0.f; g_deg_h[i] = 0.f; }
    if (i < 2 * NTOT) { g_s1f[i] = 0.f; g_s1r[i] = 0.f; g_s2f[i] = 0.f; g_s2r[i] = 0.f; }
}

__global__ void k_scat1(const int* __restrict__ h, const int* __restrict__ t,
                        const float* __restrict__ topic) {
    int e = blockIdx.x * blockDim.x + threadIdx.x;
    if (e >= NE) return;
    int hi = h[e], ti = t[e];
    atomicAdd(&g_deg_t[ti], 1.f);
    atomicAdd(&g_deg_h[hi], 1.f);
    atomicAdd(&g_s1f[2 * ti],     topic[2 * hi]);
    atomicAdd(&g_s1f[2 * ti + 1], topic[2 * hi + 1]);
    atomicAdd(&g_s1r[2 * hi],     topic[2 * ti]);
    atomicAdd(&g_s1r[2 * hi + 1], topic[2 * ti + 1]);
}

__global__ void k_norm1() {
    int i = blockIdx.x * blockDim.x + threadIdx.x;
    if (i >= NTOT) return;
    float dt = fmaxf(g_deg_t[i], 1.f), dh = fmaxf(g_deg_h[i], 1.f);
    g_f1[2 * i]     = g_s1f[2 * i] / dt;
    g_f1[2 * i + 1] = g_s1f[2 * i + 1] / dt;
    g_r1[2 * i]     = g_s1r[2 * i] / dh;
    g_r1[2 * i + 1] = g_s1r[2 * i + 1] / dh;
}

__global__ void k_scat2(const int* __restrict__ h, const int* __restrict__ t) {
    int e = blockIdx.x * blockDim.x + threadIdx.x;
    if (e >= NE) return;
    int hi = h[e], ti = t[e];
    atomicAdd(&g_s2f[2 * ti],     g_f1[2 * hi]);
    atomicAdd(&g_s2f[2 * ti + 1], g_f1[2 * hi + 1]);
    atomicAdd(&g_s2r[2 * hi],     g_r1[2 * ti]);
    atomicAdd(&g_s2r[2 * hi + 1], g_r1[2 * ti + 1]);
}

// write dde cols (256..271) of X, zero-pad included
__global__ void k_xdde(const float* __restrict__ topic) {
    int i = blockIdx.x * blockDim.x + threadIdx.x;
    if (i >= NTOT) return;
    float dt = fmaxf(g_deg_t[i], 1.f), dh = fmaxf(g_deg_h[i], 1.f);
    size_t b = (size_t)i * KP + 256;
    g_X[b + 0] = topic[2 * i];
    g_X[b + 1] = topic[2 * i + 1];
    g_X[b + 2] = g_f1[2 * i];
    g_X[b + 3] = g_f1[2 * i + 1];
    g_X[b + 4] = g_s2f[2 * i] / dt;
    g_X[b + 5] = g_s2f[2 * i + 1] / dt;
    g_X[b + 6] = g_r1[2 * i];
    g_X[b + 7] = g_r1[2 * i + 1];
    g_X[b + 8] = g_s2r[2 * i] / dh;
    g_X[b + 9] = g_s2r[2 * i + 1] / dh;
    for (int k = 10; k < 16; k++) g_X[b + k] = 0.f;
}

// write embedding cols (0..255) of X
__global__ void k_xemb(const float* __restrict__ ent, const float* __restrict__ nt) {
    size_t idx = (size_t)blockIdx.x * blockDim.x + threadIdx.x;
    int i = (int)(idx >> 8), k = (int)(idx & 255);
    if (i >= NTOT) return;
    g_X[(size_t)i * KP + k] = (i < NTEXT) ? ent[(size_t)i * 256 + k] : nt[k];
}

// ---------------- SGEMM: AB[100000][2560] = X[100000][272] @ Wfull[272][2560] ----------------
// Double-buffered smem + register prefetch. Per-output accumulation order is
// unchanged vs the single-buffered version (k strictly ascending) -> bitwise
// identical results.
__global__ void __launch_bounds__(256, 2) k_sgemm() {
    __shared__ float As[2][8][128];
    __shared__ float Bs[2][8][128];
    int tid = threadIdx.x, tx = tid % 16, ty = tid / 16;
    int n0 = blockIdx.x * 128, m0 = blockIdx.y * 128;
    float acc[8][8];
#pragma unroll
    for (int i = 0; i < 8; i++)
#pragma unroll
        for (int j = 0; j < 8; j++) acc[i][j] = 0.f;

    // preload slab 0
#pragma unroll
    for (int r = 0; r < 4; r++) {
        int idx = tid + r * 256;
        int m = idx >> 3, kk = idx & 7;
        int gm = m0 + m;
        As[0][kk][m] = (gm < NTOT) ? g_X[(size_t)gm * KP + kk] : 0.f;
    }
#pragma unroll
    for (int r = 0; r < 4; r++) {
        int idx = tid + r * 256;
        int kk = idx >> 7, n = idx & 127;
        Bs[0][kk][n] = g_Wfull[kk * COLS + n0 + n];
    }
    __syncthreads();

    const int NT = KP / 8;  // 34 slabs
    for (int kt = 0; kt < NT; kt++) {
        int cur = kt & 1, nxt = cur ^ 1;
        float ra[4], rb[4];
        if (kt + 1 < NT) {
            int k0 = (kt + 1) * 8;
#pragma unroll
            for (int r = 0; r < 4; r++) {
                int idx = tid + r * 256;
                int m = idx >> 3, kk = idx & 7;
                int gm = m0 + m;
                ra[r] = (gm < NTOT) ? g_X[(size_t)gm * KP + k0 + kk] : 0.f;
            }
#pragma unroll
            for (int r = 0; r < 4; r++) {
                int idx = tid + r * 256;
                int kk = idx >> 7, n = idx & 127;
                rb[r] = g_Wfull[(k0 + kk) * COLS + n0 + n];
            }
        }
#pragma unroll
        for (int k = 0; k < 8; k++) {
            float4 a0 = *reinterpret_cast<const float4*>(&As[cur][k][ty * 8]);
            float4 a1 = *reinterpret_cast<const float4*>(&As[cur][k][ty * 8 + 4]);
            float4 b0 = *reinterpret_cast<const float4*>(&Bs[cur][k][tx * 8]);
            float4 b1 = *reinterpret_cast<const float4*>(&Bs[cur][k][tx * 8 + 4]);
            float av[8] = {a0.x, a0.y, a0.z, a0.w, a1.x, a1.y, a1.z, a1.w};
            float bv[8] = {b0.x, b0.y, b0.z, b0.w, b1.x, b1.y, b1.z, b1.w};
#pragma unroll
            for (int i = 0; i < 8; i++)
#pragma unroll
                for (int j = 0; j < 8; j++) acc[i][j] = fmaf(av[i], bv[j], acc[i][j]);
        }
        if (kt + 1 < NT) {
#pragma unroll
            for (int r = 0; r < 4; r++) {
                int idx = tid + r * 256;
                int m = idx >> 3, kk = idx & 7;
                As[nxt][kk][m] = ra[r];
            }
#pragma unroll
            for (int r = 0; r < 4; r++) {
                int idx = tid + r * 256;
                int kk = idx >> 7, n = idx & 127;
                Bs[nxt][kk][n] = rb[r];
            }
        }
        __syncthreads();
    }
#pragma unroll
    for (int i = 0; i < 8; i++) {
        int gm = m0 + ty * 8 + i;
        if (gm < NTOT) {
#pragma unroll
            for (int j = 0; j < 8; j++)
                g_AB[(size_t)gm * COLS + n0 + tx * 8 + j] = acc[i][j];
        }
    }
}

// ---------------- edge kernel: out[e] = mean_s( relu(qv+A[h]+C[r]+B[t]+b1) . w2_s + b2_s ) ----------------
__global__ void __launch_bounds__(256) k_edge(const int* __restrict__ h,
                                              const int* __restrict__ r,
                                              const int* __restrict__ t,
                                              float* __restrict__ out) {
    __shared__ float w2sm[NS * 256];
    for (int i = threadIdx.x; i < NS * 256; i += 256) w2sm[i] = g_w2s[i];
    __syncthreads();
    int warp = threadIdx.x >> 5, lane = threadIdx.x & 31;
    int e = blockIdx.x * 8 + warp;
    if (e >= NE) return;
    int hi = h[e], ti = t[e], ri = r[e];
    const float4* ah = reinterpret_cast<const float4*>(&g_AB[(size_t)hi * COLS]);
    const float4* at = reinterpret_cast<const float4*>(&g_AB[(size_t)ti * COLS + 1280]);
    const float4* cr = reinterpret_cast<const float4*>(&g_Cp[ri * 1280]);
    const float4* w4 = reinterpret_cast<const float4*>(w2sm);
    float acc = 0.f;
#pragma unroll
    for (int u = 0; u < 10; u++) {  // 10 * 32 lanes * 4 floats = 1280
        int i4 = u * 32 + lane;
        float4 a = __ldg(ah + i4);
        float4 b = __ldg(at + i4);
        float4 c = __ldg(cr + i4);
        float4 w = w4[i4];
        acc = fmaf(fmaxf(a.x + b.x + c.x, 0.f), w.x, acc);
        acc = fmaf(fmaxf(a.y + b.y + c.y, 0.f), w.y, acc);
        acc = fmaf(fmaxf(a.z + b.z + c.z, 0.f), w.z, acc);
        acc = fmaf(fmaxf(a.w + b.w + c.w, 0.f), w.w, acc);
    }
#pragma unroll
    for (int o = 16; o; o >>= 1) acc += __shfl_xor_sync(0xffffffffu, acc, o);
    if (lane == 0) out[e] = acc / 5.0f + g_b2mean;
}

// ---------------- launch ----------------
extern "C" void kernel_launch(void* const* d_in, const int* in_sizes, int n_in,
                              void* d_out, int out_size) {
    const int* h_id = (const int*)d_in[0];
    const int* r_id = (const int*)d_in[1];
    const int* t_id = (const int*)d_in[2];
    const float* q   = (const float*)d_in[3];
    const float* ent = (const float*)d_in[4];
    // num_non_text_entities may or may not appear as an input tensor
    int k = (n_in >= 17) ? 6 : 5;
    const float* rel   = (const float*)d_in[k + 0];
    const float* topic = (const float*)d_in[k + 1];
    const float* nt    = (const float*)d_in[k + 2];
    const float* w1mu  = (const float*)d_in[k + 3];
    const float* w1rho = (const float*)d_in[k + 4];
    const float* b1mu  = (const float*)d_in[k + 5];
    const float* b1rho = (const float*)d_in[k + 6];
    const float* w2mu  = (const float*)d_in[k + 7];
    const float* w2rho = (const float*)d_in[k + 8];
    const float* b2mu  = (const float*)d_in[k + 9];
    const float* b2rho = (const float*)d_in[k + 10];
    float* out = (float*)d_out;

    // RNG + weight sampling
    k_setup_keys<<<1, 32>>>();
    k_gen_w1<<<(NS * W1N + 255) / 256, 256>>>(w1mu, w1rho);
    k_gen_small<<<1, 256>>>(b1mu, b1rho, w2mu, w2rho, b2mu, b2rho);
    k_qv<<<NS, 256>>>(q);
    k_repack<<<(KP * COLS + 255) / 256, 256>>>();
    k_crel<<<dim3(NRELS, NS), 256>>>(rel);

    // DDE segment means
    k_zero<<<(2 * NTOT + 255) / 256, 256>>>();
    k_scat1<<<(NE + 255) / 256, 256>>>(h_id, t_id, topic);
    k_norm1<<<(NTOT + 255) / 256, 256>>>();
    k_scat2<<<(NE + 255) / 256, 256>>>(h_id, t_id);
    k_xdde<<<(NTOT + 255) / 256, 256>>>(topic);
    k_xemb<<<(NTOT * 256 + 255) / 256, 256>>>(ent, nt);

    // node-level GEMM then edge pass
    k_sgemm<<<dim3(COLS / 128, (NTOT + 127) / 128), 256>>>();
    k_edge<<<(NE + 7) / 8, 256>>>(h_id, r_id, t_id, out);
}

// round 14
// speedup vs baseline: 1.0149x; 1.0149x over previous
#include <cuda_runtime.h>
#include <cstdint>

// ---------------- problem constants ----------------
#define NTEXT 90000
#define NTOT  100000
#define NE    500000
#define NRELS 500
#define NS    5           // Bayesian samples
#define KP    272         // 266 padded to 272
#define COLS  2560        // 2 sides * 5 samples * 256 hidden
#define W1N   267264      // 256*1044

// ---------------- scratch (__device__ globals; no allocs allowed) ----------------
__device__ unsigned g_sk[NS][4][2];
__device__ float g_w1s[NS][W1N];          // sampled w1, row-major [256][1044]
__device__ float g_b1s[NS][256];
__device__ float g_w2s[NS * 256];
__device__ float g_qv[NS][256];
__device__ float g_b2mean;
__device__ float g_Wfull[KP * COLS];      // GEMM B
__device__ float g_Cp[NRELS * 1280];      // per-relation: rel@w1_r.T + qv + b1
__device__ float g_X[(size_t)NTOT * KP];  // GEMM A  (~109MB)
__device__ float g_AB[(size_t)NTOT * COLS]; // GEMM C (~1.02GB)
__device__ float g_deg_t[NTOT], g_deg_h[NTOT];
__device__ float g_s1f[2 * NTOT], g_s1r[2 * NTOT], g_s2f[2 * NTOT], g_s2r[2 * NTOT];
__device__ float g_f1[2 * NTOT], g_r1[2 * NTOT];

// ---------------- threefry2x32 (JAX partitionable; validated R10) ----------------
__device__ __forceinline__ unsigned rotl32(unsigned v, int r) { return (v << r) | (v >> (32 - r)); }

__device__ __forceinline__ void tf2(unsigned k0, unsigned k1, unsigned c0, unsigned c1,
                                    unsigned& o0, unsigned& o1) {
    unsigned ks2 = k0 ^ k1 ^ 0x1BD11BDAu;
    unsigned x0 = c0 + k0, x1 = c1 + k1;
#define TFR(r) x0 += x1; x1 = rotl32(x1, r); x1 ^= x0;
    TFR(13) TFR(15) TFR(26) TFR(6)  x0 += k1;  x1 += ks2 + 1u;
    TFR(17) TFR(29) TFR(16) TFR(24) x0 += ks2; x1 += k0 + 2u;
    TFR(13) TFR(15) TFR(26) TFR(6)  x0 += k0;  x1 += k1 + 3u;
    TFR(17) TFR(29) TFR(16) TFR(24) x0 += k1;  x1 += ks2 + 4u;
    TFR(13) TFR(15) TFR(26) TFR(6)  x0 += ks2; x1 += k0 + 5u;
#undef TFR
    o0 = x0; o1 = x1;
}

__device__ __forceinline__ unsigned pbits(unsigned k0, unsigned k1, unsigned i) {
    unsigned o0, o1;
    tf2(k0, k1, 0u, i, o0, o1);
    return o0 ^ o1;
}

__device__ __forceinline__ float bits2n(unsigned bits) {
    float f = __uint_as_float((bits >> 9) | 0x3f800000u) - 1.0f;
    float u = __fadd_rn(__fmul_rn(f, 2.0f), -0.99999994f);
    u = fmaxf(u, -0.99999994f);
    return 1.41421356f * erfinvf(u);
}

__device__ __forceinline__ float softplusf(float x) {
    return fmaxf(x, 0.0f) + log1pf(expf(-fabsf(x)));
}

// ---------------- key derivation (partitionable; validated) ----------------
__global__ void k_setup_keys() {
    if (threadIdx.x == 0 && blockIdx.x == 0) {
        for (int i = 0; i < NS; i++) {
            unsigned k0, k1;
            tf2(0u, 42u, 0u, (unsigned)i, k0, k1);
            for (int j = 0; j < 4; j++)
                tf2(k0, k1, 0u, (unsigned)j, g_sk[i][j][0], g_sk[i][j][1]);
        }
    }
}

__global__ void k_gen_w1(const float* __restrict__ mu, const float* __restrict__ rho) {
    int tid = blockIdx.x * blockDim.x + threadIdx.x;
    if (tid >= NS * W1N) return;
    int s = tid / W1N, i = tid % W1N;
    unsigned b = pbits(g_sk[s][0][0], g_sk[s][0][1], (unsigned)i);
    g_w1s[s][i] = mu[i] + bits2n(b) * softplusf(rho[i]);
}

__global__ void k_gen_small(const float* __restrict__ b1mu, const float* __restrict__ b1rho,
                            const float* __restrict__ w2mu, const float* __restrict__ w2rho,
                            const float* __restrict__ b2mu, const float* __restrict__ b2rho) {
    int t = threadIdx.x;  // 0..255
    for (int s = 0; s < NS; s++) {
        unsigned bb = pbits(g_sk[s][1][0], g_sk[s][1][1], (unsigned)t);
        g_b1s[s][t] = b1mu[t] + bits2n(bb) * softplusf(b1rho[t]);
        unsigned bw = pbits(g_sk[s][2][0], g_sk[s][2][1], (unsigned)t);
        g_w2s[s * 256 + t] = w2mu[t] + bits2n(bw) * softplusf(w2rho[t]);
    }
    if (t == 0) {
        float acc = 0.f;
        for (int s = 0; s < NS; s++) {
            unsigned b2b = pbits(g_sk[s][3][0], g_sk[s][3][1], 0u);
            acc += b2mu[0] + bits2n(b2b) * softplusf(b2rho[0]);
        }
        g_b2mean = acc / 5.0f;
    }
}

__global__ void k_qv(const float* __restrict__ q) {
    int s = blockIdx.x, j = threadIdx.x;
    const float* w = &g_w1s[s][j * 1044];
    float acc = 0.f;
    for (int k = 0; k < 256; k++) acc += q[k] * w[k];
    g_qv[s][j] = acc;
}

// ---------------- repack GEMM-B: Wfull[k][side*1280 + s*256 + j] ----------------
__global__ void k_repack() {
    int idx = blockIdx.x * blockDim.x + threadIdx.x;
    if (idx >= KP * COLS) return;
    int k = idx / COLS, c = idx % COLS;
    float v = 0.f;
    if (k < 266) {
        int side = c / 1280, rem = c % 1280, s = rem / 256, j = rem % 256;
        int col = (k < 256) ? ((side ? 778 : 256) + k) : ((side ? 1034 : 512) + (k - 256));
        v = g_w1s[s][j * 1044 + col];
    }
    g_Wfull[idx] = v;
}

__global__ void k_crel(const float* __restrict__ rel) {
    int r = blockIdx.x, s = blockIdx.y, j = threadIdx.x;
    __shared__ float rsm[256];
    rsm[j] = rel[r * 256 + j];
    __syncthreads();
    const float* w = &g_w1s[s][j * 1044 + 522];
    float acc = g_b1s[s][j] + g_qv[s][j];
    for (int k = 0; k < 256; k++) acc += rsm[k] * w[k];
    g_Cp[r * 1280 + s * 256 + j] = acc;
}

// ---------------- DDE (segment means) ----------------
__global__ void k_zero() {
    int i = blockIdx.x * blockDim.x + threadIdx.x;
    if (i < NTOT) { g_deg_t[i] = 0.f; g_deg_h[i] = 0.f; }
    if (i < 2 * NTOT) { g_s1f[i] = 0.f; g_s1r[i] = 0.f; g_s2f[i] = 0.f; g_s2r[i] = 0.f; }
}

__global__ void k_scat1(const int* __restrict__ h, const int* __restrict__ t,
                        const float* __restrict__ topic) {
    int e = blockIdx.x * blockDim.x + threadIdx.x;
    if (e >= NE) return;
    int hi = h[e], ti = t[e];
    atomicAdd(&g_deg_t[ti], 1.f);
    atomicAdd(&g_deg_h[hi], 1.f);
    atomicAdd(&g_s1f[2 * ti],     topic[2 * hi]);
    atomicAdd(&g_s1f[2 * ti + 1], topic[2 * hi + 1]);
    atomicAdd(&g_s1r[2 * hi],     topic[2 * ti]);
    atomicAdd(&g_s1r[2 * hi + 1], topic[2 * ti + 1]);
}

__global__ void k_norm1() {
    int i = blockIdx.x * blockDim.x + threadIdx.x;
    if (i >= NTOT) return;
    float dt = fmaxf(g_deg_t[i], 1.f), dh = fmaxf(g_deg_h[i], 1.f);
    g_f1[2 * i]     = g_s1f[2 * i] / dt;
    g_f1[2 * i + 1] = g_s1f[2 * i + 1] / dt;
    g_r1[2 * i]     = g_s1r[2 * i] / dh;
    g_r1[2 * i + 1] = g_s1r[2 * i + 1] / dh;
}

__global__ void k_scat2(const int* __restrict__ h, const int* __restrict__ t) {
    int e = blockIdx.x * blockDim.x + threadIdx.x;
    if (e >= NE) return;
    int hi = h[e], ti = t[e];
    atomicAdd(&g_s2f[2 * ti],     g_f1[2 * hi]);
    atomicAdd(&g_s2f[2 * ti + 1], g_f1[2 * hi + 1]);
    atomicAdd(&g_s2r[2 * hi],     g_r1[2 * ti]);
    atomicAdd(&g_s2r[2 * hi + 1], g_r1[2 * ti + 1]);
}

// write dde cols (256..271) of X, zero-pad included
__global__ void k_xdde(const float* __restrict__ topic) {
    int i = blockIdx.x * blockDim.x + threadIdx.x;
    if (i >= NTOT) return;
    float dt = fmaxf(g_deg_t[i], 1.f), dh = fmaxf(g_deg_h[i], 1.f);
    size_t b = (size_t)i * KP + 256;
    g_X[b + 0] = topic[2 * i];
    g_X[b + 1] = topic[2 * i + 1];
    g_X[b + 2] = g_f1[2 * i];
    g_X[b + 3] = g_f1[2 * i + 1];
    g_X[b + 4] = g_s2f[2 * i] / dt;
    g_X[b + 5] = g_s2f[2 * i + 1] / dt;
    g_X[b + 6] = g_r1[2 * i];
    g_X[b + 7] = g_r1[2 * i + 1];
    g_X[b + 8] = g_s2r[2 * i] / dh;
    g_X[b + 9] = g_s2r[2 * i + 1] / dh;
    for (int k = 10; k < 16; k++) g_X[b + k] = 0.f;
}

// write embedding cols (0..255) of X
__global__ void k_xemb(const float* __restrict__ ent, const float* __restrict__ nt) {
    size_t idx = (size_t)blockIdx.x * blockDim.x + threadIdx.x;
    int i = (int)(idx >> 8), k = (int)(idx & 255);
    if (i >= NTOT) return;
    g_X[(size_t)i * KP + k] = (i < NTEXT) ? ent[(size_t)i * 256 + k] : nt[k];
}

// ---------------- SGEMM: AB[100000][2560] = X[100000][272] @ Wfull[272][2560] ----------------
// Double-buffered smem + register prefetch (validated R10) with the inner 8x8
// FMA block done as packed fp32x2 (FFMA2). Each lane rounds identically to
// scalar fmaf and per-output k-order is unchanged -> bitwise identical output.
__global__ void __launch_bounds__(256, 2) k_sgemm() {
    __shared__ float As[2][8][128];
    __shared__ float Bs[2][8][128];
    int tid = threadIdx.x, tx = tid % 16, ty = tid / 16;
    int n0 = blockIdx.x * 128, m0 = blockIdx.y * 128;
    unsigned long long acc2[8][4];
#pragma unroll
    for (int i = 0; i < 8; i++)
#pragma unroll
        for (int j = 0; j < 4; j++) acc2[i][j] = 0ull;

    // preload slab 0
#pragma unroll
    for (int r = 0; r < 4; r++) {
        int idx = tid + r * 256;
        int m = idx >> 3, kk = idx & 7;
        int gm = m0 + m;
        As[0][kk][m] = (gm < NTOT) ? g_X[(size_t)gm * KP + kk] : 0.f;
    }
#pragma unroll
    for (int r = 0; r < 4; r++) {
        int idx = tid + r * 256;
        int kk = idx >> 7, n = idx & 127;
        Bs[0][kk][n] = g_Wfull[kk * COLS + n0 + n];
    }
    __syncthreads();

    const int NT = KP / 8;  // 34 slabs
    for (int kt = 0; kt < NT; kt++) {
        int cur = kt & 1, nxt = cur ^ 1;
        float ra[4], rb[4];
        if (kt + 1 < NT) {
            int k0 = (kt + 1) * 8;
#pragma unroll
            for (int r = 0; r < 4; r++) {
                int idx = tid + r * 256;
                int m = idx >> 3, kk = idx & 7;
                int gm = m0 + m;
                ra[r] = (gm < NTOT) ? g_X[(size_t)gm * KP + k0 + kk] : 0.f;
            }
#pragma unroll
            for (int r = 0; r < 4; r++) {
                int idx = tid + r * 256;
                int kk = idx >> 7, n = idx & 127;
                rb[r] = g_Wfull[(k0 + kk) * COLS + n0 + n];
            }
        }
#pragma unroll
        for (int k = 0; k < 8; k++) {
            float4 a0 = *reinterpret_cast<const float4*>(&As[cur][k][ty * 8]);
            float4 a1 = *reinterpret_cast<const float4*>(&As[cur][k][ty * 8 + 4]);
            float4 b0 = *reinterpret_cast<const float4*>(&Bs[cur][k][tx * 8]);
            float4 b1 = *reinterpret_cast<const float4*>(&Bs[cur][k][tx * 8 + 4]);
            float av[8] = {a0.x, a0.y, a0.z, a0.w, a1.x, a1.y, a1.z, a1.w};
            unsigned long long bp[4];
            asm("mov.b64 %0, {%1,%2};" : "=l"(bp[0]) : "f"(b0.x), "f"(b0.y));
            asm("mov.b64 %0, {%1,%2};" : "=l"(bp[1]) : "f"(b0.z), "f"(b0.w));
            asm("mov.b64 %0, {%1,%2};" : "=l"(bp[2]) : "f"(b1.x), "f"(b1.y));
            asm("mov.b64 %0, {%1,%2};" : "=l"(bp[3]) : "f"(b1.z), "f"(b1.w));
#pragma unroll
            for (int i = 0; i < 8; i++) {
                unsigned long long ai;
                asm("mov.b64 %0, {%1,%1};" : "=l"(ai) : "f"(av[i]));
#pragma unroll
                for (int j = 0; j < 4; j++)
                    asm("fma.rn.f32x2 %0, %1, %2, %0;" : "+l"(acc2[i][j]) : "l"(ai), "l"(bp[j]));
            }
        }
        if (kt + 1 < NT) {
#pragma unroll
            for (int r = 0; r < 4; r++) {
                int idx = tid + r * 256;
                int m = idx >> 3, kk = idx & 7;
                As[nxt][kk][m] = ra[r];
            }
#pragma unroll
            for (int r = 0; r < 4; r++) {
                int idx = tid + r * 256;
                int kk = idx >> 7, n = idx & 127;
                Bs[nxt][kk][n] = rb[r];
            }
        }
        __syncthreads();
    }
#pragma unroll
    for (int i = 0; i < 8; i++) {
        int gm = m0 + ty * 8 + i;
        if (gm < NTOT) {
            float* dst = &g_AB[(size_t)gm * COLS + n0 + tx * 8];
#pragma unroll
            for (int j = 0; j < 4; j++) {
                float lo, hi;
                asm("mov.b64 {%0,%1}, %2;" : "=f"(lo), "=f"(hi) : "l"(acc2[i][j]));
                dst[2 * j]     = lo;
                dst[2 * j + 1] = hi;
            }
        }
    }
}

// ---------------- edge kernel: out[e] = mean_s( relu(qv+A[h]+C[r]+B[t]+b1) . w2_s + b2_s ) ----------------
__global__ void __launch_bounds__(256) k_edge(const int* __restrict__ h,
                                              const int* __restrict__ r,
                                              const int* __restrict__ t,
                                              float* __restrict__ out) {
    __shared__ float w2sm[NS * 256];
    for (int i = threadIdx.x; i < NS * 256; i += 256) w2sm[i] = g_w2s[i];
    __syncthreads();
    int warp = threadIdx.x >> 5, lane = threadIdx.x & 31;
    int e = blockIdx.x * 8 + warp;
    if (e >= NE) return;
    int hi = h[e], ti = t[e], ri = r[e];
    const float4* ah = reinterpret_cast<const float4*>(&g_AB[(size_t)hi * COLS]);
    const float4* at = reinterpret_cast<const float4*>(&g_AB[(size_t)ti * COLS + 1280]);
    const float4* cr = reinterpret_cast<const float4*>(&g_Cp[ri * 1280]);
    const float4* w4 = reinterpret_cast<const float4*>(w2sm);
    float acc = 0.f;
#pragma unroll
    for (int u = 0; u < 10; u++) {  // 10 * 32 lanes * 4 floats = 1280
        int i4 = u * 32 + lane;
        float4 a = __ldg(ah + i4);
        float4 b = __ldg(at + i4);
        float4 c = __ldg(cr + i4);
        float4 w = w4[i4];
        acc = fmaf(fmaxf(a.x + b.x + c.x, 0.f), w.x, acc);
        acc = fmaf(fmaxf(a.y + b.y + c.y, 0.f), w.y, acc);
        acc = fmaf(fmaxf(a.z + b.z + c.z, 0.f), w.z, acc);
        acc = fmaf(fmaxf(a.w + b.w + c.w, 0.f), w.w, acc);
    }
#pragma unroll
    for (int o = 16; o; o >>= 1) acc += __shfl_xor_sync(0xffffffffu, acc, o);
    if (lane == 0) out[e] = acc / 5.0f + g_b2mean;
}

// ---------------- launch ----------------
extern "C" void kernel_launch(void* const* d_in, const int* in_sizes, int n_in,
                              void* d_out, int out_size) {
    const int* h_id = (const int*)d_in[0];
    const int* r_id = (const int*)d_in[1];
    const int* t_id = (const int*)d_in[2];
    const float* q   = (const float*)d_in[3];
    const float* ent = (const float*)d_in[4];
    int k = (n_in >= 17) ? 6 : 5;
    const float* rel   = (const float*)d_in[k + 0];
    const float* topic = (const float*)d_in[k + 1];
    const float* nt    = (const float*)d_in[k + 2];
    const float* w1mu  = (const float*)d_in[k + 3];
    const float* w1rho = (const float*)d_in[k + 4];
    const float* b1mu  = (const float*)d_in[k + 5];
    const float* b1rho = (const float*)d_in[k + 6];
    const float* w2mu  = (const float*)d_in[k + 7];
    const float* w2rho = (const float*)d_in[k + 8];
    const float* b2mu  = (const float*)d_in[k + 9];
    const float* b2rho = (const float*)d_in[k + 10];
    float* out = (float*)d_out;

    // RNG + weight sampling
    k_setup_keys<<<1, 32>>>();
    k_gen_w1<<<(NS * W1N + 255) / 256, 256>>>(w1mu, w1rho);
    k_gen_small<<<1, 256>>>(b1mu, b1rho, w2mu, w2rho, b2mu, b2rho);
    k_qv<<<NS, 256>>>(q);
    k_repack<<<(KP * COLS + 255) / 256, 256>>>();
    k_crel<<<dim3(NRELS, NS), 256>>>(rel);

    // DDE segment means
    k_zero<<<(2 * NTOT + 255) / 256, 256>>>();
    k_scat1<<<(NE + 255) / 256, 256>>>(h_id, t_id, topic);
    k_norm1<<<(NTOT + 255) / 256, 256>>>();
    k_scat2<<<(NE + 255) / 256, 256>>>(h_id, t_id);
    k_xdde<<<(NTOT + 255) / 256, 256>>>(topic);
    k_xemb<<<(NTOT * 256 + 255) / 256, 256>>>(ent, nt);

    // node-level GEMM (FFMA2) then edge pass
    k_sgemm<<<dim3(COLS / 128, (NTOT + 127) / 128), 256>>>();
    k_edge<<<(NE + 7) / 8, 256>>>(h_id, r_id, t_id, out);
}

// round 16
// speedup vs baseline: 1.8117x; 1.7851x over previous
#include <cuda_runtime.h>
#include <cuda_bf16.h>
#include <cstdint>

// ---------------- problem constants ----------------
#define NTEXT 90000
#define NTOT  100000
#define NE    500000
#define NRELS 500
#define NS    5           // Bayesian samples
#define KP3   288         // 266 padded to 288 (18 k16 steps, 9 chunks of 32)
#define CK    32
#define NCH3  9
#define AST   40          // smem row stride in bf16 (32 + 8 pad, conflict-free)
#define COLS  2560        // 2 sides * 5 samples * 256 hidden
#define W1N   267264      // 256*1044

// ---------------- scratch (__device__ globals; no allocs allowed) ----------------
__device__ unsigned g_sk[NS][4][2];
__device__ float g_w1s[NS][W1N];
__device__ float g_b1s[NS][256];
__device__ float g_w2s[NS * 256];
__device__ float g_qv[NS][256];
__device__ float g_b2mean;
__device__ __align__(16) __nv_bfloat16 g_Xh[(size_t)NTOT * KP3];
__device__ __align__(16) __nv_bfloat16 g_Xl[(size_t)NTOT * KP3];
__device__ __align__(16) __nv_bfloat16 g_Wth[(size_t)COLS * KP3];  // W^T [2560][288]
__device__ __align__(16) __nv_bfloat16 g_Wtl[(size_t)COLS * KP3];
__device__ float g_Cp[NRELS * 1280];
__device__ float g_AB[(size_t)NTOT * COLS]; // node GEMM out (~1.02GB)
__device__ float g_deg_t[NTOT], g_deg_h[NTOT];
__device__ float g_s1f[2 * NTOT], g_s1r[2 * NTOT], g_s2f[2 * NTOT], g_s2r[2 * NTOT];
__device__ float g_f1[2 * NTOT], g_r1[2 * NTOT];

// ---------------- threefry2x32 (JAX partitionable; validated) ----------------
__device__ __forceinline__ unsigned rotl32(unsigned v, int r) { return (v << r) | (v >> (32 - r)); }

__device__ __forceinline__ void tf2(unsigned k0, unsigned k1, unsigned c0, unsigned c1,
                                    unsigned& o0, unsigned& o1) {
    unsigned ks2 = k0 ^ k1 ^ 0x1BD11BDAu;
    unsigned x0 = c0 + k0, x1 = c1 + k1;
#define TFR(r) x0 += x1; x1 = rotl32(x1, r); x1 ^= x0;
    TFR(13) TFR(15) TFR(26) TFR(6)  x0 += k1;  x1 += ks2 + 1u;
    TFR(17) TFR(29) TFR(16) TFR(24) x0 += ks2; x1 += k0 + 2u;
    TFR(13) TFR(15) TFR(26) TFR(6)  x0 += k0;  x1 += k1 + 3u;
    TFR(17) TFR(29) TFR(16) TFR(24) x0 += k1;  x1 += ks2 + 4u;
    TFR(13) TFR(15) TFR(26) TFR(6)  x0 += ks2; x1 += k0 + 5u;
#undef TFR
    o0 = x0; o1 = x1;
}

__device__ __forceinline__ unsigned pbits(unsigned k0, unsigned k1, unsigned i) {
    unsigned o0, o1;
    tf2(k0, k1, 0u, i, o0, o1);
    return o0 ^ o1;
}

__device__ __forceinline__ float bits2n(unsigned bits) {
    float f = __uint_as_float((bits >> 9) | 0x3f800000u) - 1.0f;
    float u = __fadd_rn(__fmul_rn(f, 2.0f), -0.99999994f);
    u = fmaxf(u, -0.99999994f);
    return 1.41421356f * erfinvf(u);
}

__device__ __forceinline__ float softplusf(float x) {
    return fmaxf(x, 0.0f) + log1pf(expf(-fabsf(x)));
}

__device__ __forceinline__ uint32_t s2u(const void* p) {
    uint32_t a;
    asm("{ .reg .u64 t; cvta.to.shared.u64 t, %1; cvt.u32.u64 %0, t; }" : "=r"(a) : "l"(p));
    return a;
}

// ---------------- key derivation ----------------
__global__ void k_setup_keys() {
    if (threadIdx.x == 0 && blockIdx.x == 0) {
        for (int i = 0; i < NS; i++) {
            unsigned k0, k1;
            tf2(0u, 42u, 0u, (unsigned)i, k0, k1);
            for (int j = 0; j < 4; j++)
                tf2(k0, k1, 0u, (unsigned)j, g_sk[i][j][0], g_sk[i][j][1]);
        }
    }
}

__global__ void k_gen_w1(const float* __restrict__ mu, const float* __restrict__ rho) {
    int tid = blockIdx.x * blockDim.x + threadIdx.x;
    if (tid >= NS * W1N) return;
    int s = tid / W1N, i = tid % W1N;
    unsigned b = pbits(g_sk[s][0][0], g_sk[s][0][1], (unsigned)i);
    g_w1s[s][i] = mu[i] + bits2n(b) * softplusf(rho[i]);
}

__global__ void k_gen_small(const float* __restrict__ b1mu, const float* __restrict__ b1rho,
                            const float* __restrict__ w2mu, const float* __restrict__ w2rho,
                            const float* __restrict__ b2mu, const float* __restrict__ b2rho) {
    int t = threadIdx.x;
    for (int s = 0; s < NS; s++) {
        unsigned bb = pbits(g_sk[s][1][0], g_sk[s][1][1], (unsigned)t);
        g_b1s[s][t] = b1mu[t] + bits2n(bb) * softplusf(b1rho[t]);
        unsigned bw = pbits(g_sk[s][2][0], g_sk[s][2][1], (unsigned)t);
        g_w2s[s * 256 + t] = w2mu[t] + bits2n(bw) * softplusf(w2rho[t]);
    }
    if (t == 0) {
        float acc = 0.f;
        for (int s = 0; s < NS; s++) {
            unsigned b2b = pbits(g_sk[s][3][0], g_sk[s][3][1], 0u);
            acc += b2mu[0] + bits2n(b2b) * softplusf(b2rho[0]);
        }
        g_b2mean = acc / 5.0f;
    }
}

__global__ void k_qv(const float* __restrict__ q) {
    int s = blockIdx.x, j = threadIdx.x;
    const float* w = &g_w1s[s][j * 1044];
    float acc = 0.f;
    for (int k = 0; k < 256; k++) acc += q[k] * w[k];
    g_qv[s][j] = acc;
}

// ---------------- repack W^T bf16 hi/lo: Wt[c][k], c = side*1280+s*256+j ----------------
__global__ void k_repack() {
    int idx = blockIdx.x * blockDim.x + threadIdx.x;
    if (idx >= COLS * KP3) return;
    int c = idx / KP3, k = idx % KP3;
    float v = 0.f;
    if (k < 266) {
        int side = c / 1280, rem = c % 1280, s = rem / 256, j = rem % 256;
        int col = (k < 256) ? ((side ? 778 : 256) + k) : ((side ? 1034 : 512) + (k - 256));
        v = g_w1s[s][j * 1044 + col];
    }
    __nv_bfloat16 hi = __float2bfloat16_rn(v);
    g_Wth[idx] = hi;
    g_Wtl[idx] = __float2bfloat16_rn(v - __bfloat162float(hi));
}

__global__ void k_crel(const float* __restrict__ rel) {
    int r = blockIdx.x, s = blockIdx.y, j = threadIdx.x;
    __shared__ float rsm[256];
    rsm[j] = rel[r * 256 + j];
    __syncthreads();
    const float* w = &g_w1s[s][j * 1044 + 522];
    float acc = g_b1s[s][j] + g_qv[s][j];
    for (int k = 0; k < 256; k++) acc += rsm[k] * w[k];
    g_Cp[r * 1280 + s * 256 + j] = acc;
}

// ---------------- DDE (segment means) ----------------
__global__ void k_zero() {
    int i = blockIdx.x * blockDim.x + threadIdx.x;
    if (i < NTOT) { g_deg_t[i] = 0.f; g_deg_h[i] = 0.f; }
    if (i < 2 * NTOT) { g_s1f[i] = 0.f; g_s1r[i] = 0.f; g_s2f[i] = 0.f; g_s2r[i] = 0.f; }
}

__global__ void k_scat1(const int* __restrict__ h, const int* __restrict__ t,
                        const float* __restrict__ topic) {
    int e = blockIdx.x * blockDim.x + threadIdx.x;
    if (e >= NE) return;
    int hi = h[e], ti = t[e];
    atomicAdd(&g_deg_t[ti], 1.f);
    atomicAdd(&g_deg_h[hi], 1.f);
    atomicAdd(&g_s1f[2 * ti],     topic[2 * hi]);
    atomicAdd(&g_s1f[2 * ti + 1], topic[2 * hi + 1]);
    atomicAdd(&g_s1r[2 * hi],     topic[2 * ti]);
    atomicAdd(&g_s1r[2 * hi + 1], topic[2 * ti + 1]);
}

__global__ void k_norm1() {
    int i = blockIdx.x * blockDim.x + threadIdx.x;
    if (i >= NTOT) return;
    float dt = fmaxf(g_deg_t[i], 1.f), dh = fmaxf(g_deg_h[i], 1.f);
    g_f1[2 * i]     = g_s1f[2 * i] / dt;
    g_f1[2 * i + 1] = g_s1f[2 * i + 1] / dt;
    g_r1[2 * i]     = g_s1r[2 * i] / dh;
    g_r1[2 * i + 1] = g_s1r[2 * i + 1] / dh;
}

__global__ void k_scat2(const int* __restrict__ h, const int* __restrict__ t) {
    int e = blockIdx.x * blockDim.x + threadIdx.x;
    if (e >= NE) return;
    int hi = h[e], ti = t[e];
    atomicAdd(&g_s2f[2 * ti],     g_f1[2 * hi]);
    atomicAdd(&g_s2f[2 * ti + 1], g_f1[2 * hi + 1]);
    atomicAdd(&g_s2r[2 * hi],     g_r1[2 * ti]);
    atomicAdd(&g_s2r[2 * hi + 1], g_r1[2 * ti + 1]);
}

__device__ __forceinline__ void store_hilo(size_t idx, float v) {
    __nv_bfloat16 hi = __float2bfloat16_rn(v);
    g_Xh[idx] = hi;
    g_Xl[idx] = __float2bfloat16_rn(v - __bfloat162float(hi));
}

// dde cols (256..265) + zero pad (266..287)
__global__ void k_xdde(const float* __restrict__ topic) {
    int i = blockIdx.x * blockDim.x + threadIdx.x;
    if (i >= NTOT) return;
    float dt = fmaxf(g_deg_t[i], 1.f), dh = fmaxf(g_deg_h[i], 1.f);
    size_t b = (size_t)i * KP3 + 256;
    store_hilo(b + 0, topic[2 * i]);
    store_hilo(b + 1, topic[2 * i + 1]);
    store_hilo(b + 2, g_f1[2 * i]);
    store_hilo(b + 3, g_f1[2 * i + 1]);
    store_hilo(b + 4, g_s2f[2 * i] / dt);
    store_hilo(b + 5, g_s2f[2 * i + 1] / dt);
    store_hilo(b + 6, g_r1[2 * i]);
    store_hilo(b + 7, g_r1[2 * i + 1]);
    store_hilo(b + 8, g_s2r[2 * i] / dh);
    store_hilo(b + 9, g_s2r[2 * i + 1] / dh);
    __nv_bfloat16 z = __float2bfloat16_rn(0.f);
    for (int k = 10; k < 32; k++) { g_Xh[b + k] = z; g_Xl[b + k] = z; }
}

// embedding cols (0..255)
__global__ void k_xemb(const float* __restrict__ ent, const float* __restrict__ nt) {
    size_t idx = (size_t)blockIdx.x * blockDim.x + threadIdx.x;
    int i = (int)(idx >> 8), k = (int)(idx & 255);
    if (i >= NTOT) return;
    float v = (i < NTEXT) ? ent[(size_t)i * 256 + k] : nt[k];
    store_hilo((size_t)i * KP3 + k, v);
}

// ---------------- HMMA GEMM: AB = X[.,288] @ Wt[2560,288]^T, bf16 hi/lo split ----------------
// mma.sync m16n8k16 bf16->f32 (base sm_80+ PTX; executes on tensor pipe as HMMA).
#define MMA_BF16(c, a, b0v, b1v) \
    asm volatile("mma.sync.aligned.m16n8k16.row.col.f32.bf16.bf16.f32 " \
        "{%0,%1,%2,%3}, {%4,%5,%6,%7}, {%8,%9}, {%0,%1,%2,%3};" \
        : "+f"((c)[0]), "+f"((c)[1]), "+f"((c)[2]), "+f"((c)[3]) \
        : "r"((a)[0]), "r"((a)[1]), "r"((a)[2]), "r"((a)[3]), "r"(b0v), "r"(b1v))

#define LDSM4(r, addr) \
    asm volatile("ldmatrix.sync.aligned.m8n8.x4.shared.b16 {%0,%1,%2,%3}, [%4];" \
        : "=r"((r)[0]), "=r"((r)[1]), "=r"((r)[2]), "=r"((r)[3]) : "r"(addr))

// smem (bf16 units): buffer b at b*20480; Ah=+0, Al=+5120, Bh=+10240, Bl=+15360
#define SM_BUF 20480

__global__ void __launch_bounds__(256) k_mma() {
    extern __shared__ __nv_bfloat16 sm3[];
    int tid = threadIdx.x, wid = tid >> 5, lane = tid & 31;
    int wm = wid & 1, wn = wid >> 1;              // warp tile: rows wm*64, cols wn*32
    int m0 = blockIdx.y * 128, n0 = blockIdx.x * 128;

    float acc[4][4][4];
#pragma unroll
    for (int i = 0; i < 4; i++)
#pragma unroll
        for (int f = 0; f < 4; f++)
#pragma unroll
            for (int c = 0; c < 4; c++) acc[i][f][c] = 0.f;

    // per-thread global-load coords: 8 uint4; idx = tid + r*256
    // m = idx>>9 (0:Ah 1:Al 2:Bh 3:Bl), row = (idx&511)>>2, u = idx&3
    // ldmatrix lane addressing
    int sub = lane >> 3, l7 = lane & 7;
    int fr = l7 + (sub & 1) * 8;   // row within 16-block
    int fk = (sub >> 1) * 8;       // k offset within 16

    uint4 pv[8];
    // ---- load chunk 0 into regs, then smem buf 0
#pragma unroll
    for (int r = 0; r < 8; r++) {
        int idx = tid + r * 256;
        int mm = idx >> 9, row = (idx & 511) >> 2, u = idx & 3;
        uint4 v = make_uint4(0, 0, 0, 0);
        if (mm < 2) {
            int gm = m0 + row;
            if (gm < NTOT) {
                const __nv_bfloat16* src = mm ? g_Xl : g_Xh;
                v = *(const uint4*)((const char*)src + ((size_t)gm * KP3) * 2 + u * 16);
            }
        } else {
            int gn = n0 + row;
            const __nv_bfloat16* src = (mm == 2) ? g_Wth : g_Wtl;
            v = *(const uint4*)((const char*)src + ((size_t)gn * KP3) * 2 + u * 16);
        }
        pv[r] = v;
    }
#pragma unroll
    for (int r = 0; r < 8; r++) {
        int idx = tid + r * 256;
        int mm = idx >> 9, row = (idx & 511) >> 2, u = idx & 3;
        *(uint4*)&sm3[mm * 5120 + row * AST + u * 8] = pv[r];
    }
    __syncthreads();

    for (int ch = 0; ch < NCH3; ch++) {
        // prefetch next chunk to regs
        if (ch + 1 < NCH3) {
            int k0 = (ch + 1) * CK;
#pragma unroll
            for (int r = 0; r < 8; r++) {
                int idx = tid + r * 256;
                int mm = idx >> 9, row = (idx & 511) >> 2, u = idx & 3;
                uint4 v = make_uint4(0, 0, 0, 0);
                if (mm < 2) {
                    int gm = m0 + row;
                    if (gm < NTOT) {
                        const __nv_bfloat16* src = mm ? g_Xl : g_Xh;
                        v = *(const uint4*)((const char*)src + ((size_t)gm * KP3 + k0) * 2 + u * 16);
                    }
                } else {
                    int gn = n0 + row;
                    const __nv_bfloat16* src = (mm == 2) ? g_Wth : g_Wtl;
                    v = *(const uint4*)((const char*)src + ((size_t)gn * KP3 + k0) * 2 + u * 16);
                }
                pv[r] = v;
            }
        }
        int bb = (ch & 1) * SM_BUF;
#pragma unroll
        for (int ks = 0; ks < 2; ks++) {
            uint32_t Ah[4][4], Al[4][4], Bh[2][4], Bl[2][4];
#pragma unroll
            for (int i = 0; i < 4; i++) {
                uint32_t a = s2u(&sm3[bb + 0     + (wm * 64 + i * 16 + fr) * AST + ks * 16 + fk]);
                LDSM4(Ah[i], a);
                uint32_t a2 = s2u(&sm3[bb + 5120 + (wm * 64 + i * 16 + fr) * AST + ks * 16 + fk]);
                LDSM4(Al[i], a2);
            }
#pragma unroll
            for (int j = 0; j < 2; j++) {
                uint32_t b = s2u(&sm3[bb + 10240 + (wn * 32 + j * 16 + fr) * AST + ks * 16 + fk]);
                LDSM4(Bh[j], b);
                uint32_t b2 = s2u(&sm3[bb + 15360 + (wn * 32 + j * 16 + fr) * AST + ks * 16 + fk]);
                LDSM4(Bl[j], b2);
            }
            // passes: Ah*Bh, Al*Bh, Ah*Bl   (f: j=f>>1, h=f&1 -> b0=B[j][h], b1=B[j][h+2])
#pragma unroll
            for (int i = 0; i < 4; i++)
#pragma unroll
                for (int f = 0; f < 4; f++) {
                    int j = f >> 1, hh = f & 1;
                    MMA_BF16(acc[i][f], Ah[i], Bh[j][hh], Bh[j][hh + 2]);
                    MMA_BF16(acc[i][f], Al[i], Bh[j][hh], Bh[j][hh + 2]);
                    MMA_BF16(acc[i][f], Ah[i], Bl[j][hh], Bl[j][hh + 2]);
                }
        }
        if (ch + 1 < NCH3) {
            int nb = ((ch + 1) & 1) * SM_BUF;
#pragma unroll
            for (int r = 0; r < 8; r++) {
                int idx = tid + r * 256;
                int mm = idx >> 9, row = (idx & 511) >> 2, u = idx & 3;
                *(uint4*)&sm3[nb + mm * 5120 + row * AST + u * 8] = pv[r];
            }
        }
        __syncthreads();
    }

    // store accumulators
    int rbase = m0 + wm * 64 + (lane >> 2);
    int cbase = n0 + wn * 32 + (lane & 3) * 2;
#pragma unroll
    for (int i = 0; i < 4; i++) {
        int r0 = rbase + i * 16, r1 = r0 + 8;
#pragma unroll
        for (int f = 0; f < 4; f++) {
            int cc = cbase + f * 8;
            if (r0 < NTOT) *(float2*)&g_AB[(size_t)r0 * COLS + cc] = make_float2(acc[i][f][0], acc[i][f][1]);
            if (r1 < NTOT) *(float2*)&g_AB[(size_t)r1 * COLS + cc] = make_float2(acc[i][f][2], acc[i][f][3]);
        }
    }
}

// ---------------- edge kernel ----------------
__global__ void __launch_bounds__(256) k_edge(const int* __restrict__ h,
                                              const int* __restrict__ r,
                                              const int* __restrict__ t,
                                              float* __restrict__ out) {
    __shared__ float w2sm[NS * 256];
    for (int i = threadIdx.x; i < NS * 256; i += 256) w2sm[i] = g_w2s[i];
    __syncthreads();
    int warp = threadIdx.x >> 5, lane = threadIdx.x & 31;
    int e = blockIdx.x * 8 + warp;
    if (e >= NE) return;
    int hi = h[e], ti = t[e], ri = r[e];
    const float4* ah = reinterpret_cast<const float4*>(&g_AB[(size_t)hi * COLS]);
    const float4* at = reinterpret_cast<const float4*>(&g_AB[(size_t)ti * COLS + 1280]);
    const float4* cr = reinterpret_cast<const float4*>(&g_Cp[ri * 1280]);
    const float4* w4 = reinterpret_cast<const float4*>(w2sm);
    float acc = 0.f;
#pragma unroll
    for (int u = 0; u < 10; u++) {
        int i4 = u * 32 + lane;
        float4 a = __ldg(ah + i4);
        float4 b = __ldg(at + i4);
        float4 c = __ldg(cr + i4);
        float4 w = w4[i4];
        acc = fmaf(fmaxf(a.x + b.x + c.x, 0.f), w.x, acc);
        acc = fmaf(fmaxf(a.y + b.y + c.y, 0.f), w.y, acc);
        acc = fmaf(fmaxf(a.z + b.z + c.z, 0.f), w.z, acc);
        acc = fmaf(fmaxf(a.w + b.w + c.w, 0.f), w.w, acc);
    }
#pragma unroll
    for (int o = 16; o; o >>= 1) acc += __shfl_xor_sync(0xffffffffu, acc, o);
    if (lane == 0) out[e] = acc / 5.0f + g_b2mean;
}

// ---------------- launch ----------------
extern "C" void kernel_launch(void* const* d_in, const int* in_sizes, int n_in,
                              void* d_out, int out_size) {
    const int* h_id = (const int*)d_in[0];
    const int* r_id = (const int*)d_in[1];
    const int* t_id = (const int*)d_in[2];
    const float* q   = (const float*)d_in[3];
    const float* ent = (const float*)d_in[4];
    int k = (n_in >= 17) ? 6 : 5;
    const float* rel   = (const float*)d_in[k + 0];
    const float* topic = (const float*)d_in[k + 1];
    const float* nt    = (const float*)d_in[k + 2];
    const float* w1mu  = (const float*)d_in[k + 3];
    const float* w1rho = (const float*)d_in[k + 4];
    const float* b1mu  = (const float*)d_in[k + 5];
    const float* b1rho = (const float*)d_in[k + 6];
    const float* w2mu  = (const float*)d_in[k + 7];
    const float* w2rho = (const float*)d_in[k + 8];
    const float* b2mu  = (const float*)d_in[k + 9];
    const float* b2rho = (const float*)d_in[k + 10];
    float* out = (float*)d_out;

    static int smem_set = 0;
    if (!smem_set) {
        cudaFuncSetAttribute(k_mma, cudaFuncAttributeMaxDynamicSharedMemorySize,
                             2 * SM_BUF * (int)sizeof(__nv_bfloat16));
        smem_set = 1;
    }

    // RNG + weight sampling
    k_setup_keys<<<1, 32>>>();
    k_gen_w1<<<(NS * W1N + 255) / 256, 256>>>(w1mu, w1rho);
    k_gen_small<<<1, 256>>>(b1mu, b1rho, w2mu, w2rho, b2mu, b2rho);
    k_qv<<<NS, 256>>>(q);
    k_repack<<<(COLS * KP3 + 255) / 256, 256>>>();
    k_crel<<<dim3(NRELS, NS), 256>>>(rel);

    // DDE segment means
    k_zero<<<(2 * NTOT + 255) / 256, 256>>>();
    k_scat1<<<(NE + 255) / 256, 256>>>(h_id, t_id, topic);
    k_norm1<<<(NTOT + 255) / 256, 256>>>();
    k_scat2<<<(NE + 255) / 256, 256>>>(h_id, t_id);
    k_xdde<<<(NTOT + 255) / 256, 256>>>(topic);
    k_xemb<<<(NTOT * 256 + 255) / 256, 256>>>(ent, nt);

    // HMMA node GEMM then edge pass
    k_mma<<<dim3(COLS / 128, (NTOT + 127) / 128), 256,
            2 * SM_BUF * (int)sizeof(__nv_bfloat16)>>>();
    k_edge<<<(NE + 7) / 8, 256>>>(h_id, r_id, t_id, out);
}

// round 17
// speedup vs baseline: 1.9705x; 1.0876x over previous
#include <cuda_runtime.h>
#include <cuda_bf16.h>
#include <cuda_fp16.h>
#include <cstdint>

// ---------------- problem constants ----------------
#define NTEXT 90000
#define NTOT  100000
#define NE    500000
#define NRELS 500
#define NS    5           // Bayesian samples
#define KP3   288         // 266 padded to 288 (18 k16 steps, 9 chunks of 32)
#define CK    32
#define NCH3  9
#define AST   40          // smem row stride in bf16 (32 + 8 pad, conflict-free)
#define COLS  2560        // 2 sides * 5 samples * 256 hidden
#define W1N   267264      // 256*1044

// ---------------- scratch (__device__ globals; no allocs allowed) ----------------
__device__ unsigned g_sk[NS][4][2];
__device__ float g_w1s[NS][W1N];
__device__ float g_b1s[NS][256];
__device__ float g_w2s[NS * 256];
__device__ float g_qv[NS][256];
__device__ float g_b2mean;
__device__ __align__(16) __nv_bfloat16 g_Xh[(size_t)NTOT * KP3];
__device__ __align__(16) __nv_bfloat16 g_Xl[(size_t)NTOT * KP3];
__device__ __align__(16) __nv_bfloat16 g_Wth[(size_t)COLS * KP3];  // W^T [2560][288]
__device__ __align__(16) __nv_bfloat16 g_Wtl[(size_t)COLS * KP3];
__device__ float g_Cp[NRELS * 1280];
__device__ __align__(16) __half g_AB[(size_t)NTOT * COLS]; // node GEMM out (fp16, ~512MB)
__device__ float g_deg_t[NTOT], g_deg_h[NTOT];
__device__ float g_s1f[2 * NTOT], g_s1r[2 * NTOT], g_s2f[2 * NTOT], g_s2r[2 * NTOT];
__device__ float g_f1[2 * NTOT], g_r1[2 * NTOT];

// ---------------- threefry2x32 (JAX partitionable; validated) ----------------
__device__ __forceinline__ unsigned rotl32(unsigned v, int r) { return (v << r) | (v >> (32 - r)); }

__device__ __forceinline__ void tf2(unsigned k0, unsigned k1, unsigned c0, unsigned c1,
                                    unsigned& o0, unsigned& o1) {
    unsigned ks2 = k0 ^ k1 ^ 0x1BD11BDAu;
    unsigned x0 = c0 + k0, x1 = c1 + k1;
#define TFR(r) x0 += x1; x1 = rotl32(x1, r); x1 ^= x0;
    TFR(13) TFR(15) TFR(26) TFR(6)  x0 += k1;  x1 += ks2 + 1u;
    TFR(17) TFR(29) TFR(16) TFR(24) x0 += ks2; x1 += k0 + 2u;
    TFR(13) TFR(15) TFR(26) TFR(6)  x0 += k0;  x1 += k1 + 3u;
    TFR(17) TFR(29) TFR(16) TFR(24) x0 += k1;  x1 += ks2 + 4u;
    TFR(13) TFR(15) TFR(26) TFR(6)  x0 += ks2; x1 += k0 + 5u;
#undef TFR
    o0 = x0; o1 = x1;
}

__device__ __forceinline__ unsigned pbits(unsigned k0, unsigned k1, unsigned i) {
    unsigned o0, o1;
    tf2(k0, k1, 0u, i, o0, o1);
    return o0 ^ o1;
}

__device__ __forceinline__ float bits2n(unsigned bits) {
    float f = __uint_as_float((bits >> 9) | 0x3f800000u) - 1.0f;
    float u = __fadd_rn(__fmul_rn(f, 2.0f), -0.99999994f);
    u = fmaxf(u, -0.99999994f);
    return 1.41421356f * erfinvf(u);
}

__device__ __forceinline__ float softplusf(float x) {
    return fmaxf(x, 0.0f) + log1pf(expf(-fabsf(x)));
}

__device__ __forceinline__ uint32_t s2u(const void* p) {
    uint32_t a;
    asm("{ .reg .u64 t; cvta.to.shared.u64 t, %1; cvt.u32.u64 %0, t; }" : "=r"(a) : "l"(p));
    return a;
}

// ---------------- key derivation ----------------
__global__ void k_setup_keys() {
    if (threadIdx.x == 0 && blockIdx.x == 0) {
        for (int i = 0; i < NS; i++) {
            unsigned k0, k1;
            tf2(0u, 42u, 0u, (unsigned)i, k0, k1);
            for (int j = 0; j < 4; j++)
                tf2(k0, k1, 0u, (unsigned)j, g_sk[i][j][0], g_sk[i][j][1]);
        }
    }
}

__global__ void k_gen_w1(const float* __restrict__ mu, const float* __restrict__ rho) {
    int tid = blockIdx.x * blockDim.x + threadIdx.x;
    if (tid >= NS * W1N) return;
    int s = tid / W1N, i = tid % W1N;
    unsigned b = pbits(g_sk[s][0][0], g_sk[s][0][1], (unsigned)i);
    g_w1s[s][i] = mu[i] + bits2n(b) * softplusf(rho[i]);
}

__global__ void k_gen_small(const float* __restrict__ b1mu, const float* __restrict__ b1rho,
                            const float* __restrict__ w2mu, const float* __restrict__ w2rho,
                            const float* __restrict__ b2mu, const float* __restrict__ b2rho) {
    int t = threadIdx.x;
    for (int s = 0; s < NS; s++) {
        unsigned bb = pbits(g_sk[s][1][0], g_sk[s][1][1], (unsigned)t);
        g_b1s[s][t] = b1mu[t] + bits2n(bb) * softplusf(b1rho[t]);
        unsigned bw = pbits(g_sk[s][2][0], g_sk[s][2][1], (unsigned)t);
        g_w2s[s * 256 + t] = w2mu[t] + bits2n(bw) * softplusf(w2rho[t]);
    }
    if (t == 0) {
        float acc = 0.f;
        for (int s = 0; s < NS; s++) {
            unsigned b2b = pbits(g_sk[s][3][0], g_sk[s][3][1], 0u);
            acc += b2mu[0] + bits2n(b2b) * softplusf(b2rho[0]);
        }
        g_b2mean = acc / 5.0f;
    }
}

__global__ void k_qv(const float* __restrict__ q) {
    int s = blockIdx.x, j = threadIdx.x;
    const float* w = &g_w1s[s][j * 1044];
    float acc = 0.f;
    for (int k = 0; k < 256; k++) acc += q[k] * w[k];
    g_qv[s][j] = acc;
}

// ---------------- repack W^T bf16 hi/lo: Wt[c][k], c = side*1280+s*256+j ----------------
__global__ void k_repack() {
    int idx = blockIdx.x * blockDim.x + threadIdx.x;
    if (idx >= COLS * KP3) return;
    int c = idx / KP3, k = idx % KP3;
    float v = 0.f;
    if (k < 266) {
        int side = c / 1280, rem = c % 1280, s = rem / 256, j = rem % 256;
        int col = (k < 256) ? ((side ? 778 : 256) + k) : ((side ? 1034 : 512) + (k - 256));
        v = g_w1s[s][j * 1044 + col];
    }
    __nv_bfloat16 hi = __float2bfloat16_rn(v);
    g_Wth[idx] = hi;
    g_Wtl[idx] = __float2bfloat16_rn(v - __bfloat162float(hi));
}

__global__ void k_crel(const float* __restrict__ rel) {
    int r = blockIdx.x, s = blockIdx.y, j = threadIdx.x;
    __shared__ float rsm[256];
    rsm[j] = rel[r * 256 + j];
    __syncthreads();
    const float* w = &g_w1s[s][j * 1044 + 522];
    float acc = g_b1s[s][j] + g_qv[s][j];
    for (int k = 0; k < 256; k++) acc += rsm[k] * w[k];
    g_Cp[r * 1280 + s * 256 + j] = acc;
}

// ---------------- DDE (segment means) ----------------
__global__ void k_zero() {
    int i = blockIdx.x * blockDim.x + threadIdx.x;
    if (i < NTOT) { g_deg_t[i] = 0.f; g_deg_h[i] = 0.f; }
    if (i < 2 * NTOT) { g_s1f[i] = 0.f; g_s1r[i] = 0.f; g_s2f[i] = 0.f; g_s2r[i] = 0.f; }
}

__global__ void k_scat1(const int* __restrict__ h, const int* __restrict__ t,
                        const float* __restrict__ topic) {
    int e = blockIdx.x * blockDim.x + threadIdx.x;
    if (e >= NE) return;
    int hi = h[e], ti = t[e];
    atomicAdd(&g_deg_t[ti], 1.f);
    atomicAdd(&g_deg_h[hi], 1.f);
    atomicAdd(&g_s1f[2 * ti],     topic[2 * hi]);
    atomicAdd(&g_s1f[2 * ti + 1], topic[2 * hi + 1]);
    atomicAdd(&g_s1r[2 * hi],     topic[2 * ti]);
    atomicAdd(&g_s1r[2 * hi + 1], topic[2 * ti + 1]);
}

__global__ void k_norm1() {
    int i = blockIdx.x * blockDim.x + threadIdx.x;
    if (i >= NTOT) return;
    float dt = fmaxf(g_deg_t[i], 1.f), dh = fmaxf(g_deg_h[i], 1.f);
    g_f1[2 * i]     = g_s1f[2 * i] / dt;
    g_f1[2 * i + 1] = g_s1f[2 * i + 1] / dt;
    g_r1[2 * i]     = g_s1r[2 * i] / dh;
    g_r1[2 * i + 1] = g_s1r[2 * i + 1] / dh;
}

__global__ void k_scat2(const int* __restrict__ h, const int* __restrict__ t) {
    int e = blockIdx.x * blockDim.x + threadIdx.x;
    if (e >= NE) return;
    int hi = h[e], ti = t[e];
    atomicAdd(&g_s2f[2 * ti],     g_f1[2 * hi]);
    atomicAdd(&g_s2f[2 * ti + 1], g_f1[2 * hi + 1]);
    atomicAdd(&g_s2r[2 * hi],     g_r1[2 * ti]);
    atomicAdd(&g_s2r[2 * hi + 1], g_r1[2 * ti + 1]);
}

__device__ __forceinline__ void store_hilo(size_t idx, float v) {
    __nv_bfloat16 hi = __float2bfloat16_rn(v);
    g_Xh[idx] = hi;
    g_Xl[idx] = __float2bfloat16_rn(v - __bfloat162float(hi));
}

// dde cols (256..265) + zero pad (266..287)
__global__ void k_xdde(const float* __restrict__ topic) {
    int i = blockIdx.x * blockDim.x + threadIdx.x;
    if (i >= NTOT) return;
    float dt = fmaxf(g_deg_t[i], 1.f), dh = fmaxf(g_deg_h[i], 1.f);
    size_t b = (size_t)i * KP3 + 256;
    store_hilo(b + 0, topic[2 * i]);
    store_hilo(b + 1, topic[2 * i + 1]);
    store_hilo(b + 2, g_f1[2 * i]);
    store_hilo(b + 3, g_f1[2 * i + 1]);
    store_hilo(b + 4, g_s2f[2 * i] / dt);
    store_hilo(b + 5, g_s2f[2 * i + 1] / dt);
    store_hilo(b + 6, g_r1[2 * i]);
    store_hilo(b + 7, g_r1[2 * i + 1]);
    store_hilo(b + 8, g_s2r[2 * i] / dh);
    store_hilo(b + 9, g_s2r[2 * i + 1] / dh);
    __nv_bfloat16 z = __float2bfloat16_rn(0.f);
    for (int k = 10; k < 32; k++) { g_Xh[b + k] = z; g_Xl[b + k] = z; }
}

// embedding cols (0..255)
__global__ void k_xemb(const float* __restrict__ ent, const float* __restrict__ nt) {
    size_t idx = (size_t)blockIdx.x * blockDim.x + threadIdx.x;
    int i = (int)(idx >> 8), k = (int)(idx & 255);
    if (i >= NTOT) return;
    float v = (i < NTEXT) ? ent[(size_t)i * 256 + k] : nt[k];
    store_hilo((size_t)i * KP3 + k, v);
}

// ---------------- HMMA GEMM: AB = X[.,288] @ Wt[2560,288]^T, bf16 hi/lo split ----------------
#define MMA_BF16(c, a, b0v, b1v) \
    asm volatile("mma.sync.aligned.m16n8k16.row.col.f32.bf16.bf16.f32 " \
        "{%0,%1,%2,%3}, {%4,%5,%6,%7}, {%8,%9}, {%0,%1,%2,%3};" \
        : "+f"((c)[0]), "+f"((c)[1]), "+f"((c)[2]), "+f"((c)[3]) \
        : "r"((a)[0]), "r"((a)[1]), "r"((a)[2]), "r"((a)[3]), "r"(b0v), "r"(b1v))

#define LDSM4(r, addr) \
    asm volatile("ldmatrix.sync.aligned.m8n8.x4.shared.b16 {%0,%1,%2,%3}, [%4];" \
        : "=r"((r)[0]), "=r"((r)[1]), "=r"((r)[2]), "=r"((r)[3]) : "r"(addr))

#define SM_BUF 20480

__global__ void __launch_bounds__(256) k_mma() {
    extern __shared__ __nv_bfloat16 sm3[];
    int tid = threadIdx.x, wid = tid >> 5, lane = tid & 31;
    int wm = wid & 1, wn = wid >> 1;
    int m0 = blockIdx.y * 128, n0 = blockIdx.x * 128;

    float acc[4][4][4];
#pragma unroll
    for (int i = 0; i < 4; i++)
#pragma unroll
        for (int f = 0; f < 4; f++)
#pragma unroll
            for (int c = 0; c < 4; c++) acc[i][f][c] = 0.f;

    int sub = lane >> 3, l7 = lane & 7;
    int fr = l7 + (sub & 1) * 8;
    int fk = (sub >> 1) * 8;

    uint4 pv[8];
#pragma unroll
    for (int r = 0; r < 8; r++) {
        int idx = tid + r * 256;
        int mm = idx >> 9, row = (idx & 511) >> 2, u = idx & 3;
        uint4 v = make_uint4(0, 0, 0, 0);
        if (mm < 2) {
            int gm = m0 + row;
            if (gm < NTOT) {
                const __nv_bfloat16* src = mm ? g_Xl : g_Xh;
                v = *(const uint4*)((const char*)src + ((size_t)gm * KP3) * 2 + u * 16);
            }
        } else {
            int gn = n0 + row;
            const __nv_bfloat16* src = (mm == 2) ? g_Wth : g_Wtl;
            v = *(const uint4*)((const char*)src + ((size_t)gn * KP3) * 2 + u * 16);
        }
        pv[r] = v;
    }
#pragma unroll
    for (int r = 0; r < 8; r++) {
        int idx = tid + r * 256;
        int mm = idx >> 9, row = (idx & 511) >> 2, u = idx & 3;
        *(uint4*)&sm3[mm * 5120 + row * AST + u * 8] = pv[r];
    }
    __syncthreads();

    for (int ch = 0; ch < NCH3; ch++) {
        if (ch + 1 < NCH3) {
            int k0 = (ch + 1) * CK;
#pragma unroll
            for (int r = 0; r < 8; r++) {
                int idx = tid + r * 256;
                int mm = idx >> 9, row = (idx & 511) >> 2, u = idx & 3;
                uint4 v = make_uint4(0, 0, 0, 0);
                if (mm < 2) {
                    int gm = m0 + row;
                    if (gm < NTOT) {
                        const __nv_bfloat16* src = mm ? g_Xl : g_Xh;
                        v = *(const uint4*)((const char*)src + ((size_t)gm * KP3 + k0) * 2 + u * 16);
                    }
                } else {
                    int gn = n0 + row;
                    const __nv_bfloat16* src = (mm == 2) ? g_Wth : g_Wtl;
                    v = *(const uint4*)((const char*)src + ((size_t)gn * KP3 + k0) * 2 + u * 16);
                }
                pv[r] = v;
            }
        }
        int bb = (ch & 1) * SM_BUF;
#pragma unroll
        for (int ks = 0; ks < 2; ks++) {
            uint32_t Ah[4][4], Al[4][4], Bh[2][4], Bl[2][4];
#pragma unroll
            for (int i = 0; i < 4; i++) {
                uint32_t a = s2u(&sm3[bb + 0     + (wm * 64 + i * 16 + fr) * AST + ks * 16 + fk]);
                LDSM4(Ah[i], a);
                uint32_t a2 = s2u(&sm3[bb + 5120 + (wm * 64 + i * 16 + fr) * AST + ks * 16 + fk]);
                LDSM4(Al[i], a2);
            }
#pragma unroll
            for (int j = 0; j < 2; j++) {
                uint32_t b = s2u(&sm3[bb + 10240 + (wn * 32 + j * 16 + fr) * AST + ks * 16 + fk]);
                LDSM4(Bh[j], b);
                uint32_t b2 = s2u(&sm3[bb + 15360 + (wn * 32 + j * 16 + fr) * AST + ks * 16 + fk]);
                LDSM4(Bl[j], b2);
            }
#pragma unroll
            for (int i = 0; i < 4; i++)
#pragma unroll
                for (int f = 0; f < 4; f++) {
                    int j = f >> 1, hh = f & 1;
                    MMA_BF16(acc[i][f], Ah[i], Bh[j][hh], Bh[j][hh + 2]);
                    MMA_BF16(acc[i][f], Al[i], Bh[j][hh], Bh[j][hh + 2]);
                    MMA_BF16(acc[i][f], Ah[i], Bl[j][hh], Bl[j][hh + 2]);
                }
        }
        if (ch + 1 < NCH3) {
            int nb = ((ch + 1) & 1) * SM_BUF;
#pragma unroll
            for (int r = 0; r < 8; r++) {
                int idx = tid + r * 256;
                int mm = idx >> 9, row = (idx & 511) >> 2, u = idx & 3;
                *(uint4*)&sm3[nb + mm * 5120 + row * AST + u * 8] = pv[r];
            }
        }
        __syncthreads();
    }

    // store accumulators as fp16
    int rbase = m0 + wm * 64 + (lane >> 2);
    int cbase = n0 + wn * 32 + (lane & 3) * 2;
#pragma unroll
    for (int i = 0; i < 4; i++) {
        int r0 = rbase + i * 16, r1 = r0 + 8;
#pragma unroll
        for (int f = 0; f < 4; f++) {
            int cc = cbase + f * 8;
            if (r0 < NTOT)
                *(__half2*)&g_AB[(size_t)r0 * COLS + cc] = __floats2half2_rn(acc[i][f][0], acc[i][f][1]);
            if (r1 < NTOT)
                *(__half2*)&g_AB[(size_t)r1 * COLS + cc] = __floats2half2_rn(acc[i][f][2], acc[i][f][3]);
        }
    }
}

// ---------------- edge kernel (fp16 AB gathers) ----------------
__global__ void __launch_bounds__(256) k_edge(const int* __restrict__ h,
                                              const int* __restrict__ r,
                                              const int* __restrict__ t,
                                              float* __restrict__ out) {
    __shared__ float w2sm[NS * 256];
    for (int i = threadIdx.x; i < NS * 256; i += 256) w2sm[i] = g_w2s[i];
    __syncthreads();
    int warp = threadIdx.x >> 5, lane = threadIdx.x & 31;
    int e = blockIdx.x * 8 + warp;
    if (e >= NE) return;
    int hi = h[e], ti = t[e], ri = r[e];
    const uint4* ah = reinterpret_cast<const uint4*>(&g_AB[(size_t)hi * COLS]);      // 8 halves / uint4
    const uint4* at = reinterpret_cast<const uint4*>(&g_AB[(size_t)ti * COLS + 1280]);
    const float4* cr = reinterpret_cast<const float4*>(&g_Cp[ri * 1280]);
    const float4* w4 = reinterpret_cast<const float4*>(w2sm);
    float acc = 0.f;
#pragma unroll
    for (int u = 0; u < 5; u++) {  // 5 * 32 lanes * 8 halves = 1280
        int i8 = u * 32 + lane;
        uint4 av = __ldg(ah + i8);
        uint4 bv = __ldg(at + i8);
        float4 c0 = __ldg(cr + 2 * i8), c1 = __ldg(cr + 2 * i8 + 1);
        float4 w0 = w4[2 * i8], w1v = w4[2 * i8 + 1];
        const __half2* ap = reinterpret_cast<const __half2*>(&av);
        const __half2* bp = reinterpret_cast<const __half2*>(&bv);
        float2 a0 = __half22float2(ap[0]), a1 = __half22float2(ap[1]);
        float2 a2 = __half22float2(ap[2]), a3 = __half22float2(ap[3]);
        float2 b0 = __half22float2(bp[0]), b1 = __half22float2(bp[1]);
        float2 b2 = __half22float2(bp[2]), b3 = __half22float2(bp[3]);
        acc = fmaf(fmaxf(a0.x + b0.x + c0.x, 0.f), w0.x, acc);
        acc = fmaf(fmaxf(a0.y + b0.y + c0.y, 0.f), w0.y, acc);
        acc = fmaf(fmaxf(a1.x + b1.x + c0.z, 0.f), w0.z, acc);
        acc = fmaf(fmaxf(a1.y + b1.y + c0.w, 0.f), w0.w, acc);
        acc = fmaf(fmaxf(a2.x + b2.x + c1.x, 0.f), w1v.x, acc);
        acc = fmaf(fmaxf(a2.y + b2.y + c1.y, 0.f), w1v.y, acc);
        acc = fmaf(fmaxf(a3.x + b3.x + c1.z, 0.f), w1v.z, acc);
        acc = fmaf(fmaxf(a3.y + b3.y + c1.w, 0.f), w1v.w, acc);
    }
#pragma unroll
    for (int o = 16; o; o >>= 1) acc += __shfl_xor_sync(0xffffffffu, acc, o);
    if (lane == 0) out[e] = acc / 5.0f + g_b2mean;
}

// ---------------- launch ----------------
extern "C" void kernel_launch(void* const* d_in, const int* in_sizes, int n_in,
                              void* d_out, int out_size) {
    const int* h_id = (const int*)d_in[0];
    const int* r_id = (const int*)d_in[1];
    const int* t_id = (const int*)d_in[2];
    const float* q   = (const float*)d_in[3];
    const float* ent = (const float*)d_in[4];
    int k = (n_in >= 17) ? 6 : 5;
    const float* rel   = (const float*)d_in[k + 0];
    const float* topic = (const float*)d_in[k + 1];
    const float* nt    = (const float*)d_in[k + 2];
    const float* w1mu  = (const float*)d_in[k + 3];
    const float* w1rho = (const float*)d_in[k + 4];
    const float* b1mu  = (const float*)d_in[k + 5];
    const float* b1rho = (const float*)d_in[k + 6];
    const float* w2mu  = (const float*)d_in[k + 7];
    const float* w2rho = (const float*)d_in[k + 8];
    const float* b2mu  = (const float*)d_in[k + 9];
    const float* b2rho = (const float*)d_in[k + 10];
    float* out = (float*)d_out;

    static int smem_set = 0;
    if (!smem_set) {
        cudaFuncSetAttribute(k_mma, cudaFuncAttributeMaxDynamicSharedMemorySize,
                             2 * SM_BUF * (int)sizeof(__nv_bfloat16));
        smem_set = 1;
    }

    // RNG + weight sampling
    k_setup_keys<<<1, 32>>>();
    k_gen_w1<<<(NS * W1N + 255) / 256, 256>>>(w1mu, w1rho);
    k_gen_small<<<1, 256>>>(b1mu, b1rho, w2mu, w2rho, b2mu, b2rho);
    k_qv<<<NS, 256>>>(q);
    k_repack<<<(COLS * KP3 + 255) / 256, 256>>>();
    k_crel<<<dim3(NRELS, NS), 256>>>(rel);

    // DDE segment means
    k_zero<<<(2 * NTOT + 255) / 256, 256>>>();
    k_scat1<<<(NE + 255) / 256, 256>>>(h_id, t_id, topic);
    k_norm1<<<(NTOT + 255) / 256, 256>>>();
    k_scat2<<<(NE + 255) / 256, 256>>>(h_id, t_id);
    k_xdde<<<(NTOT + 255) / 256, 256>>>(topic);
    k_xemb<<<(NTOT * 256 + 255) / 256, 256>>>(ent, nt);

    // HMMA node GEMM then edge pass
    k_mma<<<dim3(COLS / 128, (NTOT + 127) / 128), 256,
            2 * SM_BUF * (int)sizeof(__nv_bfloat16)>>>();
    k_edge<<<(NE + 7) / 8, 256>>>(h_id, r_id, t_id, out);
}